// round 1
// baseline (speedup 1.0000x reference)
#include <cuda_runtime.h>
#include <cuda_bf16.h>
#include <cstdint>

// Problem constants (dataset is fixed: N=50000, E=800000, IN=128, H=64, C=16)
#define MAXN 50000
#define H 64
#define IN_F 128
#define C_OUT 16

// Scratch (device globals; no allocation allowed)
__device__ float g_deg[MAXN];          // degree (with self loop)
__device__ float g_dinv[MAXN];         // rsqrt(deg)
__device__ float g_hs1[MAXN * H];      // h1_pre * dinv
__device__ float g_acc1[MAXN * H];     // scatter accumulator conv1
__device__ float g_hs2[MAXN * H];
__device__ float g_acc2[MAXN * H];
__device__ float g_A[MAXN * H];        // h2 @ Wm1_top + bm1
__device__ float g_B[MAXN * H];        // h2 @ Wm1_bot

// ---------------- degree ----------------
__global__ void deg_init_kernel(int N) {
    int n = blockIdx.x * blockDim.x + threadIdx.x;
    if (n < N) g_deg[n] = 1.0f;  // self loop
}

__global__ void deg_count_kernel(const int* __restrict__ dst, int E) {
    int e = blockIdx.x * blockDim.x + threadIdx.x;
    if (e < E) atomicAdd(&g_deg[dst[e]], 1.0f);
}

__global__ void dinv_kernel(int N) {
    int n = blockIdx.x * blockDim.x + threadIdx.x;
    if (n < N) g_dinv[n] = rsqrtf(g_deg[n]);
}

// ---------------- conv1 GEMM: hs1 = (x @ W1) * dinv ; acc1 = hs1 (self loop)
__global__ void gemm1_kernel(const float* __restrict__ x, const float* __restrict__ W1, int N) {
    int n = blockIdx.x;
    int j = threadIdx.x;  // 0..63
    __shared__ float xs[IN_F];
    xs[j]       = x[(size_t)n * IN_F + j];
    xs[j + 64]  = x[(size_t)n * IN_F + 64 + j];
    __syncthreads();
    float a = 0.f;
#pragma unroll
    for (int k = 0; k < IN_F; k++) a += xs[k] * W1[k * H + j];
    a *= g_dinv[n];
    g_hs1[(size_t)n * H + j]  = a;
    g_acc1[(size_t)n * H + j] = a;
}

// ---------------- scatter: acc[dst] += hs[src] (16 threads / edge, float4 each)
__global__ void scatter_kernel(const int* __restrict__ src, const int* __restrict__ dst,
                               const float* __restrict__ hs, float* __restrict__ acc, int E) {
    int t = blockIdx.x * blockDim.x + threadIdx.x;
    int e = t >> 4;
    if (e >= E) return;
    int c = (t & 15) << 2;  // float4 chunk start
    int s = src[e], d = dst[e];
    float4 v = *reinterpret_cast<const float4*>(hs + (size_t)s * H + c);
    float* p = acc + (size_t)d * H + c;
    atomicAdd(p + 0, v.x);
    atomicAdd(p + 1, v.y);
    atomicAdd(p + 2, v.z);
    atomicAdd(p + 3, v.w);
}

// ---------------- conv2 GEMM (fused relu of conv1 output):
// h1 = relu(acc1*dinv + b1); hs2 = (h1 @ W2) * dinv ; acc2 = hs2
__global__ void gemm2_kernel(const float* __restrict__ W2, const float* __restrict__ b1, int N) {
    int n = blockIdx.x;
    int j = threadIdx.x;  // 0..63
    __shared__ float hrow[H];
    float di = g_dinv[n];
    hrow[j] = fmaxf(g_acc1[(size_t)n * H + j] * di + b1[j], 0.f);
    __syncthreads();
    float a = 0.f;
#pragma unroll
    for (int k = 0; k < H; k++) a += hrow[k] * W2[k * H + j];
    a *= di;
    g_hs2[(size_t)n * H + j]  = a;
    g_acc2[(size_t)n * H + j] = a;
}

// ---------------- node-side MLP precompute:
// h2 = relu(acc2*dinv + b2); A = h2 @ Wm1[0:64] + bm1; B = h2 @ Wm1[64:128]
__global__ void gemm3_kernel(const float* __restrict__ Wm1, const float* __restrict__ b2,
                             const float* __restrict__ bm1, int N) {
    int n = blockIdx.x;
    int j = threadIdx.x;
    __shared__ float h2[H];
    float di = g_dinv[n];
    h2[j] = fmaxf(g_acc2[(size_t)n * H + j] * di + b2[j], 0.f);
    __syncthreads();
    float a = 0.f, b = 0.f;
#pragma unroll
    for (int k = 0; k < H; k++) {
        float hk = h2[k];
        a += hk * Wm1[k * H + j];
        b += hk * Wm1[(k + H) * H + j];
    }
    g_A[(size_t)n * H + j] = a + bm1[j];
    g_B[(size_t)n * H + j] = b;
}

// ---------------- edge MLP: out[e] = relu(A[src]+B[dst]) @ Wm2 + bm2
__global__ void edge_kernel(const int* __restrict__ src, const int* __restrict__ dst,
                            const float* __restrict__ Wm2, const float* __restrict__ bm2,
                            float* __restrict__ out, int E) {
    __shared__ float Ws[H * C_OUT];   // 64x16
    __shared__ float bs[C_OUT];
    int tid = threadIdx.x;
    for (int i = tid; i < H * C_OUT; i += blockDim.x) Ws[i] = Wm2[i];
    if (tid < C_OUT) bs[tid] = bm2[tid];
    __syncthreads();

    int e = blockIdx.x * blockDim.x + tid;
    if (e >= E) return;
    int s = src[e], d = dst[e];
    const float4* Ap = reinterpret_cast<const float4*>(g_A + (size_t)s * H);
    const float4* Bp = reinterpret_cast<const float4*>(g_B + (size_t)d * H);

    float acc[C_OUT];
#pragma unroll
    for (int c = 0; c < C_OUT; c++) acc[c] = bs[c];

#pragma unroll
    for (int q = 0; q < H / 4; q++) {
        float4 a4 = Ap[q];
        float4 b4 = Bp[q];
        float z0 = fmaxf(a4.x + b4.x, 0.f);
        float z1 = fmaxf(a4.y + b4.y, 0.f);
        float z2 = fmaxf(a4.z + b4.z, 0.f);
        float z3 = fmaxf(a4.w + b4.w, 0.f);
        int k = q * 4;
        const float4* w0 = reinterpret_cast<const float4*>(Ws + (k + 0) * C_OUT);
        const float4* w1 = reinterpret_cast<const float4*>(Ws + (k + 1) * C_OUT);
        const float4* w2 = reinterpret_cast<const float4*>(Ws + (k + 2) * C_OUT);
        const float4* w3 = reinterpret_cast<const float4*>(Ws + (k + 3) * C_OUT);
#pragma unroll
        for (int cq = 0; cq < 4; cq++) {
            float4 r0 = w0[cq], r1 = w1[cq], r2 = w2[cq], r3 = w3[cq];
            acc[cq * 4 + 0] += z0 * r0.x + z1 * r1.x + z2 * r2.x + z3 * r3.x;
            acc[cq * 4 + 1] += z0 * r0.y + z1 * r1.y + z2 * r2.y + z3 * r3.y;
            acc[cq * 4 + 2] += z0 * r0.z + z1 * r1.z + z2 * r2.z + z3 * r3.z;
            acc[cq * 4 + 3] += z0 * r0.w + z1 * r1.w + z2 * r2.w + z3 * r3.w;
        }
    }

    float4* op = reinterpret_cast<float4*>(out + (size_t)e * C_OUT);
#pragma unroll
    for (int c = 0; c < 4; c++)
        op[c] = make_float4(acc[c * 4 + 0], acc[c * 4 + 1], acc[c * 4 + 2], acc[c * 4 + 3]);
}

extern "C" void kernel_launch(void* const* d_in, const int* in_sizes, int n_in,
                              void* d_out, int out_size) {
    const float* x    = (const float*)d_in[0];
    const int*   ei   = (const int*)d_in[1];
    const float* W1   = (const float*)d_in[2];
    const float* b1   = (const float*)d_in[3];
    const float* W2   = (const float*)d_in[4];
    const float* b2   = (const float*)d_in[5];
    const float* Wm1  = (const float*)d_in[6];
    const float* bm1  = (const float*)d_in[7];
    const float* Wm2  = (const float*)d_in[8];
    const float* bm2  = (const float*)d_in[9];
    float* out = (float*)d_out;

    int N = in_sizes[0] / IN_F;
    int E = in_sizes[1] / 2;
    const int* src = ei;
    const int* dst = ei + E;

    float* hs1;  cudaGetSymbolAddress((void**)&hs1,  g_hs1);
    float* acc1; cudaGetSymbolAddress((void**)&acc1, g_acc1);
    float* hs2;  cudaGetSymbolAddress((void**)&hs2,  g_hs2);
    float* acc2; cudaGetSymbolAddress((void**)&acc2, g_acc2);

    // degrees
    deg_init_kernel<<<(N + 255) / 256, 256>>>(N);
    deg_count_kernel<<<(E + 255) / 256, 256>>>(dst, E);
    dinv_kernel<<<(N + 255) / 256, 256>>>(N);

    // conv1
    gemm1_kernel<<<N, H>>>(x, W1, N);
    {
        long long tot = (long long)E * 16;
        scatter_kernel<<<(int)((tot + 255) / 256), 256>>>(src, dst, hs1, acc1, E);
    }

    // conv2 (relu of conv1 fused into row load)
    gemm2_kernel<<<N, H>>>(W2, b1, N);
    {
        long long tot = (long long)E * 16;
        scatter_kernel<<<(int)((tot + 255) / 256), 256>>>(src, dst, hs2, acc2, E);
    }

    // node-side MLP precompute (relu of conv2 fused)
    gemm3_kernel<<<N, H>>>(Wm1, b2, bm1, N);

    // edge MLP
    edge_kernel<<<(E + 255) / 256, 256>>>(src, dst, Wm2, bm2, out, E);
}

// round 2
// speedup vs baseline: 1.7002x; 1.7002x over previous
#include <cuda_runtime.h>
#include <cuda_bf16.h>
#include <cstdint>

// Problem constants (dataset fixed: N=50000, E=800000, IN=128, H=64, C=16)
#define MAXN 50016
#define H 64
#define IN_F 128
#define C_OUT 16

// Scratch (device globals; 16B aligned for float4 / red.v4 paths)
__device__ __align__(16) float g_deg[MAXN];
__device__ __align__(16) float g_dinv[MAXN];
__device__ __align__(16) float g_hs1[MAXN * H];
__device__ __align__(16) float g_acc1[MAXN * H];
__device__ __align__(16) float g_hs2[MAXN * H];
__device__ __align__(16) float g_acc2[MAXN * H];
__device__ __align__(16) float g_A[MAXN * H];
__device__ __align__(16) float g_B[MAXN * H];

// ---------------- degree ----------------
__global__ void deg_init_kernel(int N) {
    int n = blockIdx.x * blockDim.x + threadIdx.x;
    if (n < N) g_deg[n] = 1.0f;  // self loop
}

__global__ void deg_count_kernel(const int* __restrict__ dst, int E) {
    int e = blockIdx.x * blockDim.x + threadIdx.x;
    if (e < E) atomicAdd(&g_deg[dst[e]], 1.0f);
}

__global__ void dinv_kernel(int N) {
    int n = blockIdx.x * blockDim.x + threadIdx.x;
    if (n < N) g_dinv[n] = rsqrtf(g_deg[n]);
}

// =====================================================================
// Tiled GEMM kernels: M-tile=64, N-tile=64, 256 threads, 4x4 microtile
// =====================================================================

// conv1: hs1 = (x @ W1) * dinv ; acc1 = hs1   (K = 128, two chunks of 64)
__global__ __launch_bounds__(256) void gemm1_tiled(
    const float* __restrict__ x, const float* __restrict__ W1, int N) {
    __shared__ float As[64][68];  // [m][k]
    __shared__ float Ws[64][68];  // [k][n]
    const int tx = threadIdx.x, ty = threadIdx.y;
    const int t = ty * 16 + tx;
    const int lm = t >> 4;          // 0..15
    const int lk4 = (t & 15) * 4;   // 0..60
    const int m0 = blockIdx.x * 64;

    float acc[4][4];
#pragma unroll
    for (int i = 0; i < 4; i++)
#pragma unroll
        for (int j = 0; j < 4; j++) acc[i][j] = 0.f;

    for (int k0 = 0; k0 < IN_F; k0 += 64) {
        __syncthreads();
#pragma unroll
        for (int i = 0; i < 4; i++) {
            int m = lm + 16 * i;
            int gm = m0 + m;
            float4 v = make_float4(0.f, 0.f, 0.f, 0.f);
            if (gm < N) v = *reinterpret_cast<const float4*>(x + (size_t)gm * IN_F + k0 + lk4);
            *reinterpret_cast<float4*>(&As[m][lk4]) = v;
            int k = lm + 16 * i;
            float4 w = *reinterpret_cast<const float4*>(W1 + (size_t)(k0 + k) * H + lk4);
            *reinterpret_cast<float4*>(&Ws[k][lk4]) = w;
        }
        __syncthreads();
#pragma unroll 8
        for (int kk = 0; kk < 64; kk++) {
            float4 b4 = *reinterpret_cast<const float4*>(&Ws[kk][tx * 4]);
            float a0 = As[ty * 4 + 0][kk];
            float a1 = As[ty * 4 + 1][kk];
            float a2 = As[ty * 4 + 2][kk];
            float a3 = As[ty * 4 + 3][kk];
            acc[0][0] += a0 * b4.x; acc[0][1] += a0 * b4.y; acc[0][2] += a0 * b4.z; acc[0][3] += a0 * b4.w;
            acc[1][0] += a1 * b4.x; acc[1][1] += a1 * b4.y; acc[1][2] += a1 * b4.z; acc[1][3] += a1 * b4.w;
            acc[2][0] += a2 * b4.x; acc[2][1] += a2 * b4.y; acc[2][2] += a2 * b4.z; acc[2][3] += a2 * b4.w;
            acc[3][0] += a3 * b4.x; acc[3][1] += a3 * b4.y; acc[3][2] += a3 * b4.z; acc[3][3] += a3 * b4.w;
        }
    }

#pragma unroll
    for (int i = 0; i < 4; i++) {
        int gm = m0 + ty * 4 + i;
        if (gm < N) {
            float di = g_dinv[gm];
            float4 r = make_float4(acc[i][0] * di, acc[i][1] * di, acc[i][2] * di, acc[i][3] * di);
            *reinterpret_cast<float4*>(&g_hs1[(size_t)gm * H + tx * 4]) = r;
            *reinterpret_cast<float4*>(&g_acc1[(size_t)gm * H + tx * 4]) = r;
        }
    }
}

// conv2: h1 = relu(acc1*dinv + b1); hs2 = (h1 @ W2) * dinv; acc2 = hs2  (K=64)
__global__ __launch_bounds__(256) void gemm2_tiled(
    const float* __restrict__ W2, const float* __restrict__ b1, int N) {
    __shared__ float As[64][68];
    __shared__ float Ws[64][68];
    const int tx = threadIdx.x, ty = threadIdx.y;
    const int t = ty * 16 + tx;
    const int lm = t >> 4;
    const int lk4 = (t & 15) * 4;
    const int m0 = blockIdx.x * 64;

    float4 bb = *reinterpret_cast<const float4*>(b1 + lk4);
#pragma unroll
    for (int i = 0; i < 4; i++) {
        int m = lm + 16 * i;
        int gm = m0 + m;
        float4 v = make_float4(0.f, 0.f, 0.f, 0.f);
        if (gm < N) {
            float di = g_dinv[gm];
            float4 a = *reinterpret_cast<const float4*>(&g_acc1[(size_t)gm * H + lk4]);
            v.x = fmaxf(a.x * di + bb.x, 0.f);
            v.y = fmaxf(a.y * di + bb.y, 0.f);
            v.z = fmaxf(a.z * di + bb.z, 0.f);
            v.w = fmaxf(a.w * di + bb.w, 0.f);
        }
        *reinterpret_cast<float4*>(&As[m][lk4]) = v;
        int k = lm + 16 * i;
        float4 w = *reinterpret_cast<const float4*>(W2 + (size_t)k * H + lk4);
        *reinterpret_cast<float4*>(&Ws[k][lk4]) = w;
    }
    __syncthreads();

    float acc[4][4];
#pragma unroll
    for (int i = 0; i < 4; i++)
#pragma unroll
        for (int j = 0; j < 4; j++) acc[i][j] = 0.f;

#pragma unroll 8
    for (int kk = 0; kk < 64; kk++) {
        float4 b4 = *reinterpret_cast<const float4*>(&Ws[kk][tx * 4]);
        float a0 = As[ty * 4 + 0][kk];
        float a1 = As[ty * 4 + 1][kk];
        float a2 = As[ty * 4 + 2][kk];
        float a3 = As[ty * 4 + 3][kk];
        acc[0][0] += a0 * b4.x; acc[0][1] += a0 * b4.y; acc[0][2] += a0 * b4.z; acc[0][3] += a0 * b4.w;
        acc[1][0] += a1 * b4.x; acc[1][1] += a1 * b4.y; acc[1][2] += a1 * b4.z; acc[1][3] += a1 * b4.w;
        acc[2][0] += a2 * b4.x; acc[2][1] += a2 * b4.y; acc[2][2] += a2 * b4.z; acc[2][3] += a2 * b4.w;
        acc[3][0] += a3 * b4.x; acc[3][1] += a3 * b4.y; acc[3][2] += a3 * b4.z; acc[3][3] += a3 * b4.w;
    }

#pragma unroll
    for (int i = 0; i < 4; i++) {
        int gm = m0 + ty * 4 + i;
        if (gm < N) {
            float di = g_dinv[gm];
            float4 r = make_float4(acc[i][0] * di, acc[i][1] * di, acc[i][2] * di, acc[i][3] * di);
            *reinterpret_cast<float4*>(&g_hs2[(size_t)gm * H + tx * 4]) = r;
            *reinterpret_cast<float4*>(&g_acc2[(size_t)gm * H + tx * 4]) = r;
        }
    }
}

// node MLP precompute: h2 = relu(acc2*dinv + b2)
// half=0: g_A = h2 @ Wm1[0:64]  + bm1 ; half=1: g_B = h2 @ Wm1[64:128]
__global__ __launch_bounds__(256) void gemm3_tiled(
    const float* __restrict__ Wm1, const float* __restrict__ b2,
    const float* __restrict__ bm1, int N) {
    __shared__ float As[64][68];
    __shared__ float Ws[64][68];
    const int tx = threadIdx.x, ty = threadIdx.y;
    const int t = ty * 16 + tx;
    const int lm = t >> 4;
    const int lk4 = (t & 15) * 4;
    const int m0 = blockIdx.x * 64;
    const int half = blockIdx.y;

    float4 bb = *reinterpret_cast<const float4*>(b2 + lk4);
#pragma unroll
    for (int i = 0; i < 4; i++) {
        int m = lm + 16 * i;
        int gm = m0 + m;
        float4 v = make_float4(0.f, 0.f, 0.f, 0.f);
        if (gm < N) {
            float di = g_dinv[gm];
            float4 a = *reinterpret_cast<const float4*>(&g_acc2[(size_t)gm * H + lk4]);
            v.x = fmaxf(a.x * di + bb.x, 0.f);
            v.y = fmaxf(a.y * di + bb.y, 0.f);
            v.z = fmaxf(a.z * di + bb.z, 0.f);
            v.w = fmaxf(a.w * di + bb.w, 0.f);
        }
        *reinterpret_cast<float4*>(&As[m][lk4]) = v;
        int k = lm + 16 * i;
        float4 w = *reinterpret_cast<const float4*>(Wm1 + (size_t)(half * H + k) * H + lk4);
        *reinterpret_cast<float4*>(&Ws[k][lk4]) = w;
    }
    __syncthreads();

    float acc[4][4];
#pragma unroll
    for (int i = 0; i < 4; i++)
#pragma unroll
        for (int j = 0; j < 4; j++) acc[i][j] = 0.f;

#pragma unroll 8
    for (int kk = 0; kk < 64; kk++) {
        float4 b4 = *reinterpret_cast<const float4*>(&Ws[kk][tx * 4]);
        float a0 = As[ty * 4 + 0][kk];
        float a1 = As[ty * 4 + 1][kk];
        float a2 = As[ty * 4 + 2][kk];
        float a3 = As[ty * 4 + 3][kk];
        acc[0][0] += a0 * b4.x; acc[0][1] += a0 * b4.y; acc[0][2] += a0 * b4.z; acc[0][3] += a0 * b4.w;
        acc[1][0] += a1 * b4.x; acc[1][1] += a1 * b4.y; acc[1][2] += a1 * b4.z; acc[1][3] += a1 * b4.w;
        acc[2][0] += a2 * b4.x; acc[2][1] += a2 * b4.y; acc[2][2] += a2 * b4.z; acc[2][3] += a2 * b4.w;
        acc[3][0] += a3 * b4.x; acc[3][1] += a3 * b4.y; acc[3][2] += a3 * b4.z; acc[3][3] += a3 * b4.w;
    }

    float4 badd = make_float4(0.f, 0.f, 0.f, 0.f);
    if (half == 0) badd = *reinterpret_cast<const float4*>(bm1 + tx * 4);
    float* outbuf = (half == 0) ? g_A : g_B;
#pragma unroll
    for (int i = 0; i < 4; i++) {
        int gm = m0 + ty * 4 + i;
        if (gm < N) {
            float4 r = make_float4(acc[i][0] + badd.x, acc[i][1] + badd.y,
                                   acc[i][2] + badd.z, acc[i][3] + badd.w);
            *reinterpret_cast<float4*>(&outbuf[(size_t)gm * H + tx * 4]) = r;
        }
    }
}

// ---------------- scatter: acc[dst] += hs[src]  (16 threads/edge, red.v4)
__global__ void scatter_kernel(const int* __restrict__ src, const int* __restrict__ dst,
                               const float* __restrict__ hs, float* __restrict__ acc, int E) {
    int t = blockIdx.x * blockDim.x + threadIdx.x;
    int e = t >> 4;
    if (e >= E) return;
    int c = (t & 15) << 2;
    int s = src[e], d = dst[e];
    float4 v = *reinterpret_cast<const float4*>(hs + (size_t)s * H + c);
    float* p = acc + (size_t)d * H + c;
    asm volatile("red.global.add.v4.f32 [%0], {%1, %2, %3, %4};"
                 :: "l"(p), "f"(v.x), "f"(v.y), "f"(v.z), "f"(v.w) : "memory");
}

// ---------------- edge MLP: out[e] = relu(A[src]+B[dst]) @ Wm2 + bm2
__global__ void edge_kernel(const int* __restrict__ src, const int* __restrict__ dst,
                            const float* __restrict__ Wm2, const float* __restrict__ bm2,
                            float* __restrict__ out, int E) {
    __shared__ float Ws[H * C_OUT];
    __shared__ float bs[C_OUT];
    int tid = threadIdx.x;
    for (int i = tid; i < H * C_OUT; i += blockDim.x) Ws[i] = Wm2[i];
    if (tid < C_OUT) bs[tid] = bm2[tid];
    __syncthreads();

    int e = blockIdx.x * blockDim.x + tid;
    if (e >= E) return;
    int s = src[e], d = dst[e];
    const float4* Ap = reinterpret_cast<const float4*>(g_A + (size_t)s * H);
    const float4* Bp = reinterpret_cast<const float4*>(g_B + (size_t)d * H);

    float acc[C_OUT];
#pragma unroll
    for (int c = 0; c < C_OUT; c++) acc[c] = bs[c];

#pragma unroll
    for (int q = 0; q < H / 4; q++) {
        float4 a4 = Ap[q];
        float4 b4 = Bp[q];
        float z0 = fmaxf(a4.x + b4.x, 0.f);
        float z1 = fmaxf(a4.y + b4.y, 0.f);
        float z2 = fmaxf(a4.z + b4.z, 0.f);
        float z3 = fmaxf(a4.w + b4.w, 0.f);
        int k = q * 4;
        const float4* w0 = reinterpret_cast<const float4*>(Ws + (k + 0) * C_OUT);
        const float4* w1 = reinterpret_cast<const float4*>(Ws + (k + 1) * C_OUT);
        const float4* w2 = reinterpret_cast<const float4*>(Ws + (k + 2) * C_OUT);
        const float4* w3 = reinterpret_cast<const float4*>(Ws + (k + 3) * C_OUT);
#pragma unroll
        for (int cq = 0; cq < 4; cq++) {
            float4 r0 = w0[cq], r1 = w1[cq], r2 = w2[cq], r3 = w3[cq];
            acc[cq * 4 + 0] += z0 * r0.x + z1 * r1.x + z2 * r2.x + z3 * r3.x;
            acc[cq * 4 + 1] += z0 * r0.y + z1 * r1.y + z2 * r2.y + z3 * r3.y;
            acc[cq * 4 + 2] += z0 * r0.z + z1 * r1.z + z2 * r2.z + z3 * r3.z;
            acc[cq * 4 + 3] += z0 * r0.w + z1 * r1.w + z2 * r2.w + z3 * r3.w;
        }
    }

    float4* op = reinterpret_cast<float4*>(out + (size_t)e * C_OUT);
#pragma unroll
    for (int c = 0; c < 4; c++)
        op[c] = make_float4(acc[c * 4 + 0], acc[c * 4 + 1], acc[c * 4 + 2], acc[c * 4 + 3]);
}

extern "C" void kernel_launch(void* const* d_in, const int* in_sizes, int n_in,
                              void* d_out, int out_size) {
    const float* x    = (const float*)d_in[0];
    const int*   ei   = (const int*)d_in[1];
    const float* W1   = (const float*)d_in[2];
    const float* b1   = (const float*)d_in[3];
    const float* W2   = (const float*)d_in[4];
    const float* b2   = (const float*)d_in[5];
    const float* Wm1  = (const float*)d_in[6];
    const float* bm1  = (const float*)d_in[7];
    const float* Wm2  = (const float*)d_in[8];
    const float* bm2  = (const float*)d_in[9];
    float* out = (float*)d_out;

    int N = in_sizes[0] / IN_F;
    int E = in_sizes[1] / 2;
    const int* src = ei;
    const int* dst = ei + E;

    float* hs1;  cudaGetSymbolAddress((void**)&hs1,  g_hs1);
    float* acc1; cudaGetSymbolAddress((void**)&acc1, g_acc1);
    float* hs2;  cudaGetSymbolAddress((void**)&hs2,  g_hs2);
    float* acc2; cudaGetSymbolAddress((void**)&acc2, g_acc2);

    int blocks_m = (N + 63) / 64;

    // degrees
    deg_init_kernel<<<(N + 255) / 256, 256>>>(N);
    deg_count_kernel<<<(E + 255) / 256, 256>>>(dst, E);
    dinv_kernel<<<(N + 255) / 256, 256>>>(N);

    // conv1
    gemm1_tiled<<<blocks_m, dim3(16, 16)>>>(x, W1, N);
    {
        long long tot = (long long)E * 16;
        scatter_kernel<<<(int)((tot + 255) / 256), 256>>>(src, dst, hs1, acc1, E);
    }

    // conv2
    gemm2_tiled<<<blocks_m, dim3(16, 16)>>>(W2, b1, N);
    {
        long long tot = (long long)E * 16;
        scatter_kernel<<<(int)((tot + 255) / 256), 256>>>(src, dst, hs2, acc2, E);
    }

    // node-side MLP precompute
    gemm3_tiled<<<dim3(blocks_m, 2), dim3(16, 16)>>>(Wm1, b2, bm1, N);

    // edge MLP
    edge_kernel<<<(E + 255) / 256, 256>>>(src, dst, Wm2, bm2, out, E);
}